// round 14
// baseline (speedup 1.0000x reference)
#include <cuda_runtime.h>

#define POOL 7
#define FW 128
#define FC 1024
#define CG (FC / 4)       // 256 float4 groups per pixel
#define TPB 64
#define QG 64             // float4 groups per channel-quarter
#define NSLOT 14          // max unique x per row (7 px * 2)

__device__ __forceinline__ void cpa16(float4* smem_dst, const float4* gmem_src, bool pred) {
    if (pred) {
        unsigned s = (unsigned)__cvta_generic_to_shared(smem_dst);
        asm volatile("cp.async.cg.shared.global [%0], [%1], 16;\n" :: "r"(s), "l"(gmem_src));
    }
}

__device__ __forceinline__ float4 bilin4(float4 tl, float4 tr, float4 bl, float4 br,
                                         float fx, float fy) {
    float4 o;
    float top, bot;
    top = tl.x + (tr.x - tl.x) * fx;
    bot = bl.x + (br.x - bl.x) * fx;
    o.x = top + (bot - top) * fy;
    top = tl.y + (tr.y - tl.y) * fx;
    bot = bl.y + (br.y - bl.y) * fx;
    o.y = top + (bot - top) * fy;
    top = tl.z + (tr.z - tl.z) * fx;
    bot = bl.z + (br.z - bl.z) * fx;
    o.z = top + (bot - top) * fy;
    top = tl.w + (tr.w - tl.w) * fx;
    bot = bl.w + (br.w - bl.w) * fx;
    o.w = top + (bot - top) * fy;
    return o;
}

__global__ __launch_bounds__(TPB)
void roi_row_pipe_kernel(const float* __restrict__ feat,
                         const float* __restrict__ rois,
                         float* __restrict__ out) {
    // buf[s]      : row y0, unique-x slot s
    // buf[NSLOT+s]: row y1, unique-x slot s
    // thread t only writes/reads lane [.][t] -> no __syncthreads needed
    __shared__ float4 buf[2 * NSLOT][QG];        // 28 KB

    const int py  = blockIdx.x;                  // 0..6
    const int q   = blockIdx.y;                  // 0..3 channel quarter
    const int roi = blockIdx.z;                  // 0..511
    const int tid = threadIdx.x;
    const int c   = q * QG + tid;                // float4 group 0..255

    const float4 r = __ldg(((const float4*)rois) + roi);
    const int ymin = (int)r.x;
    const int xmin = (int)r.y;
    const int ymax = (int)r.z;
    const int xmax = (int)r.w;

    const int ylim = ymax - ymin;
    const int xlim = xmax - xmin;
    const float hs = (float)(ylim + 1) / (float)POOL;
    const float ws = (float)(xlim + 1) / (float)POOL;

    const float sy = (float)py * hs;
    const int y0 = (int)floorf(sy);
    const int y1 = min(y0 + 1, ylim);
    const float fy = sy - (float)y0;
    const bool ny = (y1 != y0) && (fy != 0.0f);

    const float4* __restrict__ featv = (const float4*)feat;
    const size_t row0 = ((size_t)(ymin + y0) * FW + xmin) * CG + c;
    const size_t row1 = ((size_t)(ymin + y1) * FW + xmin) * CG + c;

    // ---- issue phase: per-px commit groups, address-level dedup ----
    int s00[POOL], s01[POOL];
    {
        int nslots = 0;
        int prevx0 = -9, prevx1 = -9;
        int ps00 = 0, ps01 = 0;
        #pragma unroll
        for (int px = 0; px < POOL; ++px) {
            const float sx = (float)px * ws;
            const int x0 = (int)floorf(sx);
            const int x1 = min(x0 + 1, xlim);
            const float fx = sx - (float)x0;
            const bool nx = (x1 != x0) && (fx != 0.0f);

            if (x0 == prevx0) {
                s00[px] = ps00;
            } else if (x0 == prevx1) {
                s00[px] = ps01;
            } else {
                s00[px] = nslots++;
                cpa16(&buf[s00[px]][tid],         featv + row0 + (size_t)x0 * CG, true);
                cpa16(&buf[NSLOT + s00[px]][tid], featv + row1 + (size_t)x0 * CG, ny);
            }
            if (nx) {
                if (x0 == prevx0 && x1 == prevx1) {
                    s01[px] = ps01;
                } else {
                    s01[px] = nslots++;
                    cpa16(&buf[s01[px]][tid],         featv + row0 + (size_t)x1 * CG, true);
                    cpa16(&buf[NSLOT + s01[px]][tid], featv + row1 + (size_t)x1 * CG, ny);
                }
                prevx1 = x1;
                ps01 = s01[px];
            } else {
                s01[px] = s00[px];
                prevx1 = -9;
            }
            prevx0 = x0;
            ps00 = s00[px];
            asm volatile("cp.async.commit_group;\n" ::: "memory");  // group per px
        }
    }

    // ---- compute phase: progressive waits overlap copies with compute ----
    float4* __restrict__ outrow =
        (float4*)(out + ((size_t)roi * (POOL * POOL) + (size_t)py * POOL) * FC) + c;

    #pragma unroll
    for (int px = 0; px < POOL; ++px) {
        asm volatile("cp.async.wait_group %0;\n" :: "n"(POOL - 1) : "memory");
        // note: immediate must be constant; emulate (6-px) by unrolled sequence below
        // (handled explicitly per iteration)
        const float sx = (float)px * ws;
        const int x0i = (int)floorf(sx);
        const float fx = sx - (float)x0i;
        const int x1i = min(x0i + 1, xlim);
        const bool nx = (x1i != x0i) && (fx != 0.0f);

        // ensure groups 0..px have landed: outstanding <= 6-px
        switch (px) {
            case 0: asm volatile("cp.async.wait_group 6;\n" ::: "memory"); break;
            case 1: asm volatile("cp.async.wait_group 5;\n" ::: "memory"); break;
            case 2: asm volatile("cp.async.wait_group 4;\n" ::: "memory"); break;
            case 3: asm volatile("cp.async.wait_group 3;\n" ::: "memory"); break;
            case 4: asm volatile("cp.async.wait_group 2;\n" ::: "memory"); break;
            case 5: asm volatile("cp.async.wait_group 1;\n" ::: "memory"); break;
            default: asm volatile("cp.async.wait_group 0;\n" ::: "memory"); break;
        }

        const float4 tl = buf[s00[px]][tid];
        const float4 tr = nx ? buf[s01[px]][tid] : tl;
        float4 bl = tl, br = tr;
        if (ny) {
            bl = buf[NSLOT + s00[px]][tid];
            br = nx ? buf[NSLOT + s01[px]][tid] : bl;
        }
        const float4 o = bilin4(tl, tr, bl, br, fx, fy);
        __stcs(outrow + (size_t)px * CG, o);
    }
}

extern "C" void kernel_launch(void* const* d_in, const int* in_sizes, int n_in,
                              void* d_out, int out_size) {
    const float* feat = (const float*)d_in[0];   // (1,128,128,1024) fp32
    const float* rois = (const float*)d_in[1];   // (512,4) fp32
    float* out = (float*)d_out;                  // (512, 7*7*1024) fp32

    dim3 grid(POOL, 4, 512);
    roi_row_pipe_kernel<<<grid, TPB>>>(feat, rois, out);
}